// round 16
// baseline (speedup 1.0000x reference)
#include <cuda_runtime.h>
#include <math.h>

#define NCOL 22
#define NEMB 12
#define D    64
#define B    2048
#define NPAIR 253           // 22 diag + 231 upper pairs
#define NE2  (NEMB*NEMB)    // 144
#define SZ   (NCOL*NCOL*2*D)
#define NBLK (NPAIR + NCOL) // 275 total blocks
#define NMAINBLK 256        // phase-2 blocks (8 batches each)

// ---------------- scratch (device globals; no allocation allowed) ------------
__device__ float  g_colsq[NCOL];
__device__ float2 g_S[NPAIR * NE2];            // pairwise lookup table, 291 KB
__device__ int    g_arrive = 0;                // barrier counters (reset each call)
__device__ int    g_depart = 0;

// p -> (i,j) upper-triangular-incl-diag enumeration
__device__ __forceinline__ void pair_ij(int p, int& i, int& j) {
    int ii = 0, rem = p;
    while (rem >= NCOL - ii) { rem -= NCOL - ii; ii++; }
    i = ii; j = ii + rem;
}

// fast tanh: EX2 + RCP, safe for any x (measured rel_err ~2.7e-6 end-to-end)
__device__ __forceinline__ float tanh_fast(float x) {
    float e = __expf(-2.0f * fabsf(x));
    float t = __fdividef(1.0f - e, 1.0f + e);
    return copysignf(t, x);
}

// ---------------- single fused kernel ----------------------------------------
// Phase 1: blocks 0..252 tabulate S (pair blocks; diag also folds linear L);
//          blocks 253..274 compute colsq.
// Device-wide barrier (all 275 blocks co-resident: launch_bounds(256,2) ->
// >=2 blocks/SM x 148 SMs = 296 slots).
// Phase 2: blocks 0..255 each produce 8 batches (warp = batch, lane = 8 gathers).
__global__ void __launch_bounds__(256, 2)
k_all(const float* __restrict__ tables,
      const float* __restrict__ w1, const float* __restrict__ b1,
      const float* __restrict__ w2, const float* __restrict__ b2,
      const float* __restrict__ Wops, const float* __restrict__ Wcat,
      const float* __restrict__ aw, const int* __restrict__ features,
      float* __restrict__ out, int out_size) {
    int bid = blockIdx.x, t = threadIdx.x;
    int w = t >> 5, lane = t & 31;

    // phase-1 shared state
    __shared__ float  sTi[NEMB][D + 1];
    __shared__ float  sTj[NEMB][D + 1];
    __shared__ float  sWraw[12][D];
    __shared__ float4 sW[D];
    __shared__ float  sL[2 * D];
    __shared__ float4 s_Lred[2][128];
    __shared__ float  s_part[24];
    __shared__ float  s_n2c[NEMB];
    __shared__ float  s_w[8];
    // phase-2 shared state (distinct storage; filled pre-barrier)
    __shared__ int    s_f1[NCOL][8];   // e * NEMB (i-role)
    __shared__ int    s_f2[NCOL][8];   // e        (j-role)

    // ======================= PHASE 1 =======================
    if (bid >= NPAIR) {
        // ---- colsq[i] = sum_b n2[i, feat[i,b]], n2 computed inline ----
        int i = bid - NPAIR;
        for (int c = w; c < 24; c += 8) {              // 24 half-row chunks
            float x = tables[i * NEMB * D + c * 32 + lane];
            float sq = x * x;
#pragma unroll
            for (int o = 16; o; o >>= 1) sq += __shfl_xor_sync(0xffffffffu, sq, o);
            if (lane == 0) s_part[c] = sq;
        }
        __syncthreads();
        if (t < NEMB) s_n2c[t] = s_part[2 * t] + s_part[2 * t + 1];
        __syncthreads();
        float sum = 0.f;
        for (int b = t; b < B; b += 256)
            sum += s_n2c[features[i * B + b]];
#pragma unroll
        for (int o = 16; o; o >>= 1) sum += __shfl_xor_sync(0xffffffffu, sum, o);
        if (lane == 0) s_w[w] = sum;
        __syncthreads();
        if (t == 0) {
            float v = 0.f;
            for (int k = 0; k < 8; k++) v += s_w[k];
            g_colsq[i] = v;
        }
    } else {
        int p = bid;
        int i, j; pair_ij(p, i, j);
        bool diag = (i == j);

        // ---- A0: T tiles inline (3 elements per column per thread) ----
        {
            float W1[8], B1[8], W2v[8];
#pragma unroll
            for (int h = 0; h < 8; h++) { W1[h] = w1[h]; B1[h] = b1[h]; W2v[h] = w2[h]; }
            float B2v = b2[0];
#pragma unroll
            for (int r = 0; r < 3; r++) {
                int n = t + r * 256;                   // < 768
                float xi = tables[i * NEMB * D + n];
                float xj = tables[j * NEMB * D + n];
                float fi = B2v, fj = B2v;
#pragma unroll
                for (int h = 0; h < 8; h++) {
                    fi += W2v[h] * tanh_fast(xi * W1[h] + B1[h]);
                    fj += W2v[h] * tanh_fast(xj * W1[h] + B1[h]);
                }
                sTi[n >> 6][n & 63] = fi;
                sTj[n >> 6][n & 63] = fj;
            }
        }
        // ---- A1: 12 raw weight rows {Wm,Wmax,Wmin} x {ij,ji} x {o0,o1} ----
        {
            int rij = (i * NCOL + j) * 2, rji = (j * NCOL + i) * 2;
            for (int idx = t; idx < 12 * D; idx += 256) {
                int r = idx >> 6, d = idx & 63;
                int op = 1 + (r >> 2);
                int sub = r & 3;
                int row = (sub < 2) ? rij : rji;
                int o   = sub & 1;
                sWraw[r][d] = Wops[op * SZ + (row + o) * D + d];
            }
        }
        // ---- A2 (diag only): linear fold partials, 2 parts x 128 slots ----
        if (diag) {
            int slot = t & 127, part = t >> 7;         // 2 parts x 11 j's
            int o = slot >> 6, d = slot & 63;
            float sp = 0.f, smx = 0.f, smn = 0.f, sct = 0.f;
#pragma unroll
            for (int k = 0; k < 11; k++) {
                int j2 = part * 11 + k;
                int ij = ((i * NCOL + j2) * 2 + o) * D + d;
                int ji = ((j2 * NCOL + i) * 2 + o) * D + d;
                sp  += Wops[ij]          + Wops[ji];
                smx += Wops[2 * SZ + ij] + Wops[2 * SZ + ji];
                smn += Wops[3 * SZ + ij] + Wops[3 * SZ + ji];
                sct += Wcat[((i * NCOL + j2) * 2 + o) * (2 * D) + d]
                     + Wcat[((j2 * NCOL + i) * 2 + o) * (2 * D) + D + d];
            }
            s_Lred[part][slot] = make_float4(sp, smx, smn, sct);
        }
        __syncthreads();

        // ---- B: symmetrize weights; diag: combine L ----
        {
            int comp = t >> 6, d = t & 63;             // 4 x 64 = 256 exactly
            float aw1 = aw[1], aw2 = aw[2], aw3 = aw[3];
            float v;
            if (comp < 2) {
                v = diag ? aw1 * sWraw[comp][d]
                         : aw1 * (sWraw[comp][d] + sWraw[2 + comp][d]);
            } else if (diag) {
                v = 0.f;
            } else {
                int o = comp - 2;
                v = 0.5f * (aw2 * (sWraw[4 + o][d] + sWraw[6 + o][d])
                          - aw3 * (sWraw[8 + o][d] + sWraw[10 + o][d]));
            }
            float* f = (float*)&sW[d];
            f[comp] = v;
        }
        if (diag && t < 128) {
            float4 a = s_Lred[0][t], b = s_Lred[1][t];
            sL[t] = aw[0] * (a.x + b.x) + aw[4] * (a.w + b.w)
                  + 0.5f * (aw[2] * (a.y + b.y) + aw[3] * (a.z + b.z));
        }
        __syncthreads();

        // ---- C: tabulate S[p][e1][e2] ----
        if (t < NE2) {
            int e1 = t / NEMB, e2 = t % NEMB;
            bool dl = diag && (e1 == e2);
            float s0 = 0.f, s1 = 0.f, l0 = 0.f, l1 = 0.f;
#pragma unroll 4
            for (int d = 0; d < D; d++) {
                float4 wv = sW[d];
                float ti = sTi[e1][d], tj = sTj[e2][d];
                float m = ti * tj;
                float a = fabsf(ti - tj);
                s0 = fmaf(wv.x, m, fmaf(wv.z, a, s0));
                s1 = fmaf(wv.y, m, fmaf(wv.w, a, s1));
                if (dl) { l0 = fmaf(ti, sL[d], l0); l1 = fmaf(ti, sL[D + d], l1); }
            }
            if (dl) { s0 += l0; s1 += l1; }
            g_S[p * NE2 + t] = make_float2(s0, s1);
        }
    }

    // ---- pre-barrier: prefetch phase-2 features (independent of S) ----
    if (bid < NMAINBLK) {
        for (int idx = t; idx < NCOL * 8; idx += 256) {
            int e = features[(idx >> 3) * B + bid * 8 + (idx & 7)];
            s_f1[idx >> 3][idx & 7] = e * NEMB;
            s_f2[idx >> 3][idx & 7] = e;
        }
    }

    // ======================= BARRIER =======================
    __threadfence();
    __syncthreads();
    if (t == 0) {
        atomicAdd(&g_arrive, 1);
        while (atomicAdd(&g_arrive, 0) < NBLK) __nanosleep(64);
    }
    __syncthreads();
    __threadfence();

    // ======================= PHASE 2 =======================
    if (bid < NMAINBLK) {
        int b = bid * 8 + w;               // warp = batch
        int p0 = lane * 8;
        int i, j; pair_ij(p0, i, j);

        int off[8], pv[8];
#pragma unroll
        for (int k = 0; k < 8; k++) {
            int ic = (i < NCOL) ? i : NCOL - 1;
            int jc = (j < NCOL) ? j : NCOL - 1;
            pv[k]  = p0 + k;
            off[k] = ((pv[k] < NPAIR) ? pv[k] : NPAIR - 1) * NE2
                   + s_f1[ic][w] + s_f2[jc][w];
            j++; if (j >= NCOL) { i++; j = i; }
        }
        float2 v[8];
#pragma unroll
        for (int k = 0; k < 8; k++) v[k] = __ldg(&g_S[off[k]]);

        float a0 = 0.f, a1 = 0.f;
#pragma unroll
        for (int k = 0; k < 8; k++)
            if (pv[k] < NPAIR) { a0 += v[k].x; a1 += v[k].y; }

#pragma unroll
        for (int o = 16; o; o >>= 1) {
            a0 += __shfl_xor_sync(0xffffffffu, a0, o);
            a1 += __shfl_xor_sync(0xffffffffu, a1, o);
        }
        if (lane == 0) { out[b * 2] = a0; out[b * 2 + 1] = a1; }

        // regularizer scalar (colsq ready after barrier)
        if (bid == 0 && w == 0 && out_size > 2 * B) {
            float vv = (lane < NCOL) ? sqrtf(g_colsq[lane]) : 0.f;
#pragma unroll
            for (int o = 16; o; o >>= 1) vv += __shfl_xor_sync(0xffffffffu, vv, o);
            if (lane == 0) out[2 * B] = 0.001f * (2.0f * NCOL) * vv;
        }
    }

    // ---- depart + reset for next graph replay ----
    __syncthreads();
    if (t == 0) {
        int old = atomicAdd(&g_depart, 1);
        if (old == NBLK - 1) {             // truly last block
            g_arrive = 0;
            g_depart = 0;
            __threadfence();
        }
    }
}

// ---------------- launch -----------------------------------------------------
extern "C" void kernel_launch(void* const* d_in, const int* in_sizes, int n_in,
                              void* d_out, int out_size) {
    const int*   features = (const int*)  d_in[0];
    const float* tables   = (const float*)d_in[1];
    const float* w1       = (const float*)d_in[2];
    const float* b1       = (const float*)d_in[3];
    const float* w2       = (const float*)d_in[4];
    const float* b2       = (const float*)d_in[5];
    const float* Wops     = (const float*)d_in[6];
    const float* Wcat     = (const float*)d_in[7];
    const float* aw       = (const float*)d_in[8];
    float* out = (float*)d_out;

    k_all<<<NBLK, 256>>>(tables, w1, b1, w2, b2, Wops, Wcat, aw,
                         features, out, out_size);
}

// round 17
// speedup vs baseline: 1.0215x; 1.0215x over previous
#include <cuda_runtime.h>
#include <math.h>

#define NCOL 22
#define NEMB 12
#define D    64
#define B    2048
#define NPAIR 253           // 22 diag + 231 upper pairs
#define NE2  (NEMB*NEMB)    // 144
#define SZ   (NCOL*NCOL*2*D)
#define NBLK (NPAIR + NCOL) // 275 blocks, all co-resident (2/SM x 148 = 296)
#define NP2  128            // phase-2 blocks, 16 batches each

// ---------------- scratch (device globals; no allocation allowed) ------------
__device__ float2 g_S[NPAIR * NE2];            // pairwise lookup table, 291 KB
__device__ float  g_T[NCOL * NEMB * D];        // f(tables), produced once
__device__ float  g_Lin[NCOL * NEMB * 2];      // folded linear term [i][e][o]
__device__ float  g_colsq[NCOL];
__device__ int    g_tdone  = 0;                // T-ready flag (22 producers)
__device__ int    g_arrive = 0;                // device barrier
__device__ int    g_depart = 0;

__device__ __forceinline__ void pair_ij(int p, int& i, int& j) {
    int ii = 0, rem = p;
    while (rem >= NCOL - ii) { rem -= NCOL - ii; ii++; }
    i = ii; j = ii + rem;
}

__device__ __forceinline__ float tanh_fast(float x) {
    float e = __expf(-2.0f * fabsf(x));
    float t = __fdividef(1.0f - e, 1.0f + e);
    return copysignf(t, x);
}

__global__ void __launch_bounds__(256, 2)
k_all(const float* __restrict__ tables,
      const float* __restrict__ w1, const float* __restrict__ b1,
      const float* __restrict__ w2, const float* __restrict__ b2,
      const float* __restrict__ Wops, const float* __restrict__ Wcat,
      const float* __restrict__ aw, const int* __restrict__ features,
      float* __restrict__ out, int out_size) {
    int bid = blockIdx.x, t = threadIdx.x;
    int w = t >> 5, lane = t & 31;

    // pair-role smem
    __shared__ float  sTi[NEMB][D + 1];
    __shared__ float  sTj[NEMB][D + 1];
    __shared__ float  sWraw[12][D];
    __shared__ float4 sW[D];
    // tail-role (T producer + L + colsq) smem
    __shared__ float  sX[NEMB][D + 1];     // raw tables column
    __shared__ float  sTo[NEMB][D + 1];    // own T column
    __shared__ float4 sL4[8][32][4];       // fold partials [grp][slot][{p,x,n,c}]
    __shared__ float  sL[2 * D];
    __shared__ float  s_part[24];
    __shared__ float  s_n2[NEMB];
    __shared__ float  s_sc[8];
    // phase-2 smem
    __shared__ int    s_m1[NCOL][16];      // e*NEMB
    __shared__ int    s_m2[NCOL][16];      // e
    __shared__ float  s_red[8][16][2];
    __shared__ float  s_lin[16][2];

    // ======================= PHASE 1 =======================
    if (bid < NPAIR) {
        // -------- pair block --------
        int i, j; pair_ij(bid, i, j);
        bool diag = (i == j);

        // A1: 12 raw weight rows via one round of float4 (192 loads)
        if (t < 192) {
            int r = t >> 4, q = t & 15;
            int op = 1 + (r >> 2);              // 0->Wm,1->Wmax,2->Wmin
            int sub = r & 3;
            int rij = (i * NCOL + j) * 2, rji = (j * NCOL + i) * 2;
            int row = (sub < 2) ? rij : rji;
            int o   = sub & 1;
            float4 v = *(const float4*)&Wops[op * SZ + (row + o) * D + q * 4];
            sWraw[r][q * 4 + 0] = v.x; sWraw[r][q * 4 + 1] = v.y;
            sWraw[r][q * 4 + 2] = v.z; sWraw[r][q * 4 + 3] = v.w;
        }
        // wait for T producers (overlaps with the loads above in flight)
        if (t == 0) {
            while (atomicAdd(&g_tdone, 0) < NCOL) __nanosleep(32);
        }
        __syncthreads();
        __threadfence();
        // load T columns from L2
        for (int idx = t; idx < NEMB * D; idx += 256) {
            sTi[idx >> 6][idx & 63] = g_T[i * NEMB * D + idx];
            sTj[idx >> 6][idx & 63] = g_T[j * NEMB * D + idx];
        }
        __syncthreads();
        // B: symmetrize weights (4 comps x 64 d = 256)
        {
            int comp = t >> 6, d = t & 63;
            float aw1 = aw[1], aw2 = aw[2], aw3 = aw[3];
            float v;
            if (comp < 2) {
                v = diag ? aw1 * sWraw[comp][d]
                         : aw1 * (sWraw[comp][d] + sWraw[2 + comp][d]);
            } else if (diag) {
                v = 0.f;
            } else {
                int o = comp - 2;
                v = 0.5f * (aw2 * (sWraw[4 + o][d] + sWraw[6 + o][d])
                          - aw3 * (sWraw[8 + o][d] + sWraw[10 + o][d]));
            }
            float* f = (float*)&sW[d];
            f[comp] = v;
        }
        __syncthreads();
        // C: tabulate S (no linear fold here anymore)
        if (t < NE2) {
            int e1 = t / NEMB, e2 = t % NEMB;
            float s0 = 0.f, s1 = 0.f;
#pragma unroll 4
            for (int d = 0; d < D; d++) {
                float4 wv = sW[d];
                float ti = sTi[e1][d], tj = sTj[e2][d];
                float m = ti * tj;
                float a = fabsf(ti - tj);
                s0 = fmaf(wv.x, m, fmaf(wv.z, a, s0));
                s1 = fmaf(wv.y, m, fmaf(wv.w, a, s1));
            }
            g_S[bid * NE2 + t] = make_float2(s0, s1);
        }
    } else {
        // -------- tail block: T producer + L fold + Lin + colsq --------
        int i = bid - NPAIR;

        // front-issue: features (8 ints) + raw table column (float4)
        int fv[8];
#pragma unroll
        for (int k = 0; k < 8; k++) fv[k] = features[i * B + k * 256 + t];
        if (t < 192) {
            float4 xv = *(const float4*)&tables[i * NEMB * D + t * 4];
            int n = t * 4;
            sX[n >> 6][(n & 63) + 0] = xv.x; sX[n >> 6][(n & 63) + 1] = xv.y;
            sX[n >> 6][(n & 63) + 2] = xv.z; sX[n >> 6][(n & 63) + 3] = xv.w;
        }
        __syncthreads();
        // T column: tanh of 3 elems/thread; publish early
        {
            float W1[8], B1[8], W2v[8];
#pragma unroll
            for (int h = 0; h < 8; h++) { W1[h] = w1[h]; B1[h] = b1[h]; W2v[h] = w2[h]; }
            float B2v = b2[0];
#pragma unroll
            for (int r = 0; r < 3; r++) {
                int n = t + r * 256;
                float x = sX[n >> 6][n & 63];
                float acc = B2v;
#pragma unroll
                for (int h = 0; h < 8; h++) acc += W2v[h] * tanh_fast(x * W1[h] + B1[h]);
                sTo[n >> 6][n & 63] = acc;
                g_T[i * NEMB * D + n] = acc;
            }
        }
        // n2 per e-row (24 half-rows, warp-reduced) — from raw x
        for (int c = w; c < 24; c += 8) {
            float x = sX[c >> 1][(c & 1) * 32 + lane];
            float sq = x * x;
#pragma unroll
            for (int o = 16; o; o >>= 1) sq += __shfl_xor_sync(0xffffffffu, sq, o);
            if (lane == 0) s_part[c] = sq;
        }
        __threadfence();
        __syncthreads();
        if (t == 0) atomicAdd(&g_tdone, 1);    // T[i] published

        // L fold: grp(8) x slot(32 = o*16+q), float4 over d; <=3 j per thread
        {
            int grp = t >> 5, slot = t & 31;
            int o = slot >> 4, q = slot & 15;
            float4 ap = {0,0,0,0}, ax = {0,0,0,0}, an = {0,0,0,0}, ac = {0,0,0,0};
            for (int jj = grp; jj < NCOL; jj += 8) {
                int rij = ((i * NCOL + jj) * 2 + o) * D + q * 4;
                int rji = ((jj * NCOL + i) * 2 + o) * D + q * 4;
                float4 p1 = *(const float4*)&Wops[rij];
                float4 p2 = *(const float4*)&Wops[rji];
                float4 x1 = *(const float4*)&Wops[2 * SZ + rij];
                float4 x2 = *(const float4*)&Wops[2 * SZ + rji];
                float4 n1 = *(const float4*)&Wops[3 * SZ + rij];
                float4 n2 = *(const float4*)&Wops[3 * SZ + rji];
                float4 c1 = *(const float4*)&Wcat[((i * NCOL + jj) * 2 + o) * (2 * D) + q * 4];
                float4 c2 = *(const float4*)&Wcat[((jj * NCOL + i) * 2 + o) * (2 * D) + D + q * 4];
                ap.x += p1.x + p2.x; ap.y += p1.y + p2.y; ap.z += p1.z + p2.z; ap.w += p1.w + p2.w;
                ax.x += x1.x + x2.x; ax.y += x1.y + x2.y; ax.z += x1.z + x2.z; ax.w += x1.w + x2.w;
                an.x += n1.x + n2.x; an.y += n1.y + n2.y; an.z += n1.z + n2.z; an.w += n1.w + n2.w;
                ac.x += c1.x + c2.x; ac.y += c1.y + c2.y; ac.z += c1.z + c2.z; ac.w += c1.w + c2.w;
            }
            sL4[grp][slot][0] = ap; sL4[grp][slot][1] = ax;
            sL4[grp][slot][2] = an; sL4[grp][slot][3] = ac;
        }
        if (t < NEMB) s_n2[t] = s_part[2 * t] + s_part[2 * t + 1];
        __syncthreads();
        // combine fold -> sL
        if (t < 32) {
            float aw0 = aw[0], aw2 = aw[2], aw3 = aw[3], aw4 = aw[4];
            float4 P = {0,0,0,0}, X = {0,0,0,0}, N = {0,0,0,0}, C = {0,0,0,0};
#pragma unroll
            for (int g = 0; g < 8; g++) {
                float4 a = sL4[g][t][0]; P.x += a.x; P.y += a.y; P.z += a.z; P.w += a.w;
                float4 b = sL4[g][t][1]; X.x += b.x; X.y += b.y; X.z += b.z; X.w += b.w;
                float4 c = sL4[g][t][2]; N.x += c.x; N.y += c.y; N.z += c.z; N.w += c.w;
                float4 e = sL4[g][t][3]; C.x += e.x; C.y += e.y; C.z += e.z; C.w += e.w;
            }
            int o = t >> 4, q = t & 15;
            float* dst = &sL[o * 64 + q * 4];
            dst[0] = aw0 * P.x + aw4 * C.x + 0.5f * (aw2 * X.x + aw3 * N.x);
            dst[1] = aw0 * P.y + aw4 * C.y + 0.5f * (aw2 * X.y + aw3 * N.y);
            dst[2] = aw0 * P.z + aw4 * C.z + 0.5f * (aw2 * X.z + aw3 * N.z);
            dst[3] = aw0 * P.w + aw4 * C.w + 0.5f * (aw2 * X.w + aw3 * N.w);
        }
        __syncthreads();
        // colsq
        {
            float sum = 0.f;
#pragma unroll
            for (int k = 0; k < 8; k++) sum += s_n2[fv[k]];
#pragma unroll
            for (int o = 16; o; o >>= 1) sum += __shfl_xor_sync(0xffffffffu, sum, o);
            if (lane == 0) s_sc[w] = sum;
        }
        // Lin[e][o] = sum_d sL[o*64+d] * sTo[e][d]
        if (t < 192) {
            int e = t >> 4, o = (t >> 3) & 1, c = t & 7;
            float acc = 0.f;
#pragma unroll
            for (int dd = 0; dd < 8; dd++) {
                int d = c * 8 + dd;
                acc += sL[o * 64 + d] * sTo[e][d];
            }
            acc += __shfl_xor_sync(0xffffffffu, acc, 1);
            acc += __shfl_xor_sync(0xffffffffu, acc, 2);
            acc += __shfl_xor_sync(0xffffffffu, acc, 4);
            if (c == 0) g_Lin[(i * NEMB + e) * 2 + o] = acc;
        }
        __syncthreads();
        if (t == 0) {
            float v = 0.f;
            for (int k = 0; k < 8; k++) v += s_sc[k];
            g_colsq[i] = v;
        }
    }

    // ---- pre-barrier: prefetch phase-2 features ----
    if (bid < NP2) {
        int b0 = bid * 16;
        for (int idx = t; idx < NCOL * 16; idx += 256) {
            int e = features[(idx >> 4) * B + b0 + (idx & 15)];
            s_m1[idx >> 4][idx & 15] = e * NEMB;
            s_m2[idx >> 4][idx & 15] = e;
        }
    }

    // ======================= BARRIER =======================
    __threadfence();
    __syncthreads();
    if (t == 0) {
        atomicAdd(&g_arrive, 1);
        while (atomicAdd(&g_arrive, 0) < NBLK) __nanosleep(64);
    }
    __syncthreads();
    __threadfence();

    // ======================= PHASE 2 =======================
    if (bid < NP2) {
        int b0 = bid * 16;
        int s = lane >> 4, bl = lane & 15;     // 2 pair-streams x 16 batches
        int p0 = w * 32 + s;                    // pairs p0, p0+2, ..., p0+30
        int i, j; pair_ij(p0, i, j);

        float a0 = 0.f, a1 = 0.f;
#pragma unroll
        for (int k = 0; k < 16; k++) {
            int p = p0 + 2 * k;
            int pc = (p < NPAIR) ? p : NPAIR - 1;
            int ic = (i < NCOL) ? i : NCOL - 1;
            int jc = (j < NCOL) ? j : NCOL - 1;
            float2 v = __ldg(&g_S[pc * NE2 + s_m1[ic][bl] + s_m2[jc][bl]]);
            if (p < NPAIR) { a0 += v.x; a1 += v.y; }
            j++; if (j >= NCOL) { i++; j = i; }
            j++; if (j >= NCOL) { i++; j = i; }
        }
        a0 += __shfl_xor_sync(0xffffffffu, a0, 16);
        a1 += __shfl_xor_sync(0xffffffffu, a1, 16);
        if (s == 0) { s_red[w][bl][0] = a0; s_red[w][bl][1] = a1; }

        // linear term: warp 0, lanes = (2 i-chunks x 16 batches)
        if (w == 0) {
            int c = lane >> 4, bl2 = lane & 15;
            float l0 = 0.f, l1 = 0.f;
            for (int ii = c * 11; ii < c * 11 + 11; ii++) {
                float2 lv = __ldg((const float2*)&g_Lin[(ii * NEMB + s_m2[ii][bl2]) * 2]);
                l0 += lv.x; l1 += lv.y;
            }
            l0 += __shfl_xor_sync(0xffffffffu, l0, 16);
            l1 += __shfl_xor_sync(0xffffffffu, l1, 16);
            if (c == 0) { s_lin[bl2][0] = l0; s_lin[bl2][1] = l1; }
        }
        __syncthreads();
        if (t < 16) {
            float r0 = s_lin[t][0], r1 = s_lin[t][1];
#pragma unroll
            for (int ww = 0; ww < 8; ww++) { r0 += s_red[ww][t][0]; r1 += s_red[ww][t][1]; }
            int b = b0 + t;
            out[b * 2] = r0; out[b * 2 + 1] = r1;
        }
        // regularizer scalar
        if (bid == 0 && w == 1 && out_size > 2 * B) {
            float vv = (lane < NCOL) ? sqrtf(g_colsq[lane]) : 0.f;
#pragma unroll
            for (int o = 16; o; o >>= 1) vv += __shfl_xor_sync(0xffffffffu, vv, o);
            if (lane == 0) out[2 * B] = 0.001f * (2.0f * NCOL) * vv;
        }
    }

    // ---- depart + reset for next graph replay ----
    __syncthreads();
    if (t == 0) {
        int old = atomicAdd(&g_depart, 1);
        if (old == NBLK - 1) {
            g_arrive = 0;
            g_depart = 0;
            g_tdone  = 0;
            __threadfence();
        }
    }
}

// ---------------- launch -----------------------------------------------------
extern "C" void kernel_launch(void* const* d_in, const int* in_sizes, int n_in,
                              void* d_out, int out_size) {
    const int*   features = (const int*)  d_in[0];
    const float* tables   = (const float*)d_in[1];
    const float* w1       = (const float*)d_in[2];
    const float* b1       = (const float*)d_in[3];
    const float* w2       = (const float*)d_in[4];
    const float* b2       = (const float*)d_in[5];
    const float* Wops     = (const float*)d_in[6];
    const float* Wcat     = (const float*)d_in[7];
    const float* aw       = (const float*)d_in[8];
    float* out = (float*)d_out;

    k_all<<<NBLK, 256>>>(tables, w1, b1, w2, b2, Wops, Wcat, aw,
                         features, out, out_size);
}